// round 15
// baseline (speedup 1.0000x reference)
#include <cuda_runtime.h>
#include <cuda_bf16.h>
#include <cstdint>
#include <math.h>

#define B_ 2
#define S_ 1024
#define D_ 512
#define H_ 8
#define DH_ 64
#define L_ 8
#define F_ 2048
#define V_ 32000
#define C_ 4
#define M_ (B_*S_)          // 2048 rows
#define TCH 64
#define NCH (S_/TCH)
#define NTOT 65536000       // M_*V_

#define WQKVO_SZ (D_*D_)
#define LW  (4*WQKVO_SZ + D_*F_ + F_*D_)
#define WOUT_OFF (L_*LW)
#define TOTW (WOUT_OFF + V_*D_)

// ---------------- scratch (device globals; no allocation allowed) ----------
__device__ float g_x [M_*D_];
__device__ float g_x1[M_*D_];
__device__ float g_q [M_*D_];
__device__ float g_k [M_*D_];
__device__ float g_v [M_*D_];
__device__ float g_kv[B_*H_*NCH*DH_*DH_];
__device__ float g_z [B_*H_*NCH*DH_];
__device__ unsigned long long g_am[M_];
__device__ __nv_bfloat16 g_wb[2ull*TOTW];   // weight hi plane, then lo plane
__device__ __nv_bfloat16 g_ah[M_*F_];       // activation hi
__device__ __nv_bfloat16 g_al[M_*F_];       // activation lo
__device__ __nv_bfloat16 g_gh[M_*F_];       // gelu(W1) hi
__device__ __nv_bfloat16 g_gl[M_*F_];       // gelu(W1) lo

// ---------------- helpers --------------------------------------------------
__device__ __forceinline__ void split2(float a, float b,
                                       __nv_bfloat16* hi, __nv_bfloat16* lo)
{
    __nv_bfloat16 h0 = __float2bfloat16(a);
    __nv_bfloat16 h1 = __float2bfloat16(b);
    *(__nv_bfloat162*)hi = __nv_bfloat162(h0, h1);
    *(__nv_bfloat162*)lo = __nv_bfloat162(__float2bfloat16(a - __bfloat162float(h0)),
                                          __float2bfloat16(b - __bfloat162float(h1)));
}

__device__ __forceinline__ void cpa16(uint32_t s, const void* g) {
    asm volatile("cp.async.cg.shared.global [%0], [%1], 16;" :: "r"(s), "l"(g));
}
__device__ __forceinline__ void ldsm4(unsigned* r, uint32_t a) {
    asm volatile("ldmatrix.sync.aligned.m8n8.x4.shared.b16 {%0,%1,%2,%3}, [%4];"
                 : "=r"(r[0]), "=r"(r[1]), "=r"(r[2]), "=r"(r[3]) : "r"(a));
}

// ---------------- embedding + positional (+ split) -------------------------
__global__ __launch_bounds__(128) void embed_k(const int* __restrict__ inputs,
                                               const float* __restrict__ emb,
                                               const float* __restrict__ pos,
                                               float* __restrict__ x,
                                               __nv_bfloat16* __restrict__ ah,
                                               __nv_bfloat16* __restrict__ al)
{
    int row = blockIdx.x;
    int s = row % S_;
    int tok = inputs[row];
    int tid = threadIdx.x;
    float4 e = *(const float4*)(emb + (size_t)tok*D_ + tid*4);
    float4 p = *(const float4*)(pos + (size_t)s*D_ + tid*4);
    float4 o;
    o.x = e.x + p.x; o.y = e.y + p.y; o.z = e.z + p.z; o.w = e.w + p.w;
    size_t off = (size_t)row*D_ + tid*4;
    *(float4*)(x + off) = o;
    split2(o.x, o.y, ah + off,     al + off);
    split2(o.z, o.w, ah + off + 2, al + off + 2);
}

// -------- weight transpose + split core: W[K][N] fp32 -> hi/lo [N][K] -----
__device__ __forceinline__ void wsplit_tile(const float* __restrict__ W,
                                            __nv_bfloat16* __restrict__ hi,
                                            __nv_bfloat16* __restrict__ lo,
                                            int K, int N, int n0, int k0)
{
    __shared__ float t[32][33];
    int tx = threadIdx.x, ty = threadIdx.y;     // (32,8)
#pragma unroll
    for (int i = 0; i < 32; i += 8)
        t[ty+i][tx] = W[(size_t)(k0+ty+i)*N + n0+tx];
    __syncthreads();
#pragma unroll
    for (int i = 0; i < 32; i += 8) {
        float v = t[tx][ty+i];
        __nv_bfloat16 h = __float2bfloat16(v);
        __nv_bfloat16 l = __float2bfloat16(v - __bfloat162float(h));
        size_t o = (size_t)(n0+ty+i)*K + k0+tx;
        hi[o] = h; lo[o] = l;
    }
}

__global__ __launch_bounds__(256) void wsplit_qkvo_k(
    const float* __restrict__ Wq, const float* __restrict__ Wk,
    const float* __restrict__ Wv, const float* __restrict__ Wo,
    __nv_bfloat16* __restrict__ hi, __nv_bfloat16* __restrict__ lo)
{
    int z = blockIdx.z;
    int l = z >> 2, which = z & 3;
    const float* src = (which == 0) ? Wq : (which == 1) ? Wk : (which == 2) ? Wv : Wo;
    src += (size_t)l * D_ * D_;
    size_t dsto = (size_t)l * LW + (size_t)which * WQKVO_SZ;
    wsplit_tile(src, hi + dsto, lo + dsto, D_, D_, blockIdx.x*32, blockIdx.y*32);
}

__global__ __launch_bounds__(256) void wsplit_w1_k(
    const float* __restrict__ W1,
    __nv_bfloat16* __restrict__ hi, __nv_bfloat16* __restrict__ lo)
{
    int l = blockIdx.z;
    const float* src = W1 + (size_t)l * D_ * F_;
    size_t dsto = (size_t)l * LW + 4*WQKVO_SZ;
    wsplit_tile(src, hi + dsto, lo + dsto, D_, F_, blockIdx.x*32, blockIdx.y*32);
}

__global__ __launch_bounds__(256) void wsplit_w2_k(
    const float* __restrict__ W2,
    __nv_bfloat16* __restrict__ hi, __nv_bfloat16* __restrict__ lo)
{
    int l = blockIdx.z;
    const float* src = W2 + (size_t)l * F_ * D_;
    size_t dsto = (size_t)l * LW + 4*WQKVO_SZ + (size_t)D_*F_;
    wsplit_tile(src, hi + dsto, lo + dsto, F_, D_, blockIdx.x*32, blockIdx.y*32);
}

__global__ __launch_bounds__(256) void wsplit_wout_k(
    const float* __restrict__ W,
    __nv_bfloat16* __restrict__ hi, __nv_bfloat16* __restrict__ lo)
{
    wsplit_tile(W, hi, lo, D_, V_, blockIdx.x*32, blockIdx.y*32);
}

// ---------------- Threefry-2x32-20 (JAX PRNG, key (0,42)) -----------------
__device__ __forceinline__ unsigned rotl32(unsigned x, int d) {
    return __funnelshift_l(x, x, d);
}
__device__ __forceinline__ void threefry_0_42(unsigned x0, unsigned x1,
                                              unsigned& o0, unsigned& o1)
{
    const unsigned k0 = 0u, k1 = 42u;
    const unsigned k2 = 0x1BD11BDAu ^ k0 ^ k1;
    x0 += k0; x1 += k1;
#define TF_R4(ra,rb,rc,rd) \
    x0 += x1; x1 = rotl32(x1, ra); x1 ^= x0; \
    x0 += x1; x1 = rotl32(x1, rb); x1 ^= x0; \
    x0 += x1; x1 = rotl32(x1, rc); x1 ^= x0; \
    x0 += x1; x1 = rotl32(x1, rd); x1 ^= x0;
    TF_R4(13,15,26,6);  x0 += k1; x1 += k2 + 1u;
    TF_R4(17,29,16,24); x0 += k2; x1 += k0 + 2u;
    TF_R4(13,15,26,6);  x0 += k0; x1 += k1 + 3u;
    TF_R4(17,29,16,24); x0 += k1; x1 += k2 + 4u;
    TF_R4(13,15,26,6);  x0 += k2; x1 += k0 + 5u;
#undef TF_R4
    o0 = x0; o1 = x1;
}
__device__ __forceinline__ float gumbel_from_bits(unsigned bits)
{
    float f = __uint_as_float((bits >> 9) | 0x3f800000u) - 1.0f;
    f = fmaxf(f, 1.17549435e-38f);
    return -logf(-logf(f));
}
__device__ __forceinline__ unsigned long long packkey(float v, int idx)
{
    unsigned u = __float_as_uint(v);
    u = (u & 0x80000000u) ? ~u : (u | 0x80000000u);
    return ((unsigned long long)u << 32) | (unsigned)(0xFFFFFFFFu - (unsigned)idx);
}
__device__ __forceinline__ float gumbel_at(unsigned cnt)
{
    unsigned o0, o1;
    threefry_0_42(0u, cnt, o0, o1);
    return gumbel_from_bits(o0 ^ o1);   // partitionable 32-bit path
}

// ---------------- split-bf16 tensor-core GEMM v3 ---------------------------
// C = (Ah+Al)(Bh+Bl)^T ~= AhBh + AhBl + AlBh  (lo*lo dropped)
// K-tile 32, STAGES-deep cp.async pipeline, ldmatrix fragment loads.
// MODE 0: fp32 out (+bias,+res) | MODE 1: gelu -> bf16 hi/lo | MODE 2: +gumbel argmax
#define MMA16816(d, a, b0, b1)                                              \
    asm volatile("mma.sync.aligned.m16n8k16.row.col.f32.bf16.bf16.f32 "     \
                 "{%0,%1,%2,%3}, {%4,%5,%6,%7}, {%8,%9}, {%0,%1,%2,%3};"    \
                 : "+f"(d[0]), "+f"(d[1]), "+f"(d[2]), "+f"(d[3])           \
                 : "r"(a[0]), "r"(a[1]), "r"(a[2]), "r"(a[3]),              \
                   "r"(b0), "r"(b1))

template<int BM, int BN, int THREADS, int WMS, int WNS, int MODE, int STAGES>
__device__ __forceinline__ void bmma_body(
    const __nv_bfloat16* __restrict__ Ah, const __nv_bfloat16* __restrict__ Al,
    const __nv_bfloat16* __restrict__ Bh, const __nv_bfloat16* __restrict__ Bl,
    const float* __restrict__ bias, const float* __restrict__ res,
    float* __restrict__ Cm,
    __nv_bfloat16* __restrict__ Chh, __nv_bfloat16* __restrict__ Cll,
    unsigned long long* __restrict__ am,
    int Nd, int Kd)
{
    constexpr int MFR = BM / (WMS * 16);
    constexpr int NFR = BN / (WNS * 8);
    constexpr int ROWS = 2 * (BM + BN);        // smem rows: Ah|Al|Bh|Bl
    constexpr int TILEB = ROWS * 80;           // bytes per buffer (32h + 8h pad)
    constexpr int NLD = ROWS * 4 / THREADS;    // 16B cp.async per thread per tile

    extern __shared__ char smem_raw[];
    unsigned long long* sbest = (unsigned long long*)(smem_raw + STAGES*TILEB);
    uint32_t sb;
    asm("{ .reg .u64 t; cvta.to.shared.u64 t, %1; cvt.u32.u64 %0, t; }"
        : "=r"(sb) : "l"(smem_raw));

    int tid = threadIdx.x;
    int wid = tid >> 5, lane = tid & 31;
    int wm = wid % WMS, wn = wid / WMS;
    int g = lane >> 2, tg = lane & 3;
    int t4 = lane >> 3, l8 = lane & 7;
    int row0 = blockIdx.y * BM, col0 = blockIdx.x * BN;

    // ldmatrix per-lane byte offsets (relative to buffer base)
    uint32_t aoff[MFR], boff[NFR];
#pragma unroll
    for (int mf = 0; mf < MFR; mf++)
        aoff[mf] = (uint32_t)((wm*MFR*16 + mf*16 + (t4&1)*8 + l8)*80 + (t4>>1)*16);
#pragma unroll
    for (int nf = 0; nf < NFR; nf++)
        boff[nf] = (uint32_t)(2*BM*80 + (wn*NFR*8 + nf*8 + l8)*80 + t4*16);

    float acc[MFR][NFR][4];
#pragma unroll
    for (int i = 0; i < MFR; i++)
#pragma unroll
        for (int j = 0; j < NFR; j++)
#pragma unroll
            for (int r = 0; r < 4; r++) acc[i][j][r] = 0.f;

    if (MODE == 2) {
        for (int i = tid; i < BM; i += THREADS) sbest[i] = 0ULL;
    }

    int nt = Kd >> 5;
    // always commits a group (possibly empty) so wait_group tail stays sound
    auto load_tile = [&](int t, int buf) {
        if (t < nt) {
#pragma unroll
            for (int i = 0; i < NLD; i++) {
                int j = i*THREADS + tid;
                int row = j >> 2, ch = j & 3;
                const __nv_bfloat16* gp;
                if (row < BM)             gp = Ah + (size_t)(row0 + row)*Kd;
                else if (row < 2*BM)      gp = Al + (size_t)(row0 + row - BM)*Kd;
                else if (row < 2*BM+BN)   gp = Bh + (size_t)(col0 + row - 2*BM)*Kd;
                else                      gp = Bl + (size_t)(col0 + row - 2*BM - BN)*Kd;
                cpa16(sb + buf*TILEB + row*80 + ch*16, gp + t*32 + ch*8);
            }
        }
        asm volatile("cp.async.commit_group;" ::: "memory");
    };

#pragma unroll
    for (int s = 0; s < STAGES-1; s++) load_tile(s, s);

    for (int t = 0; t < nt; t++) {
        int buf = t % STAGES;
        load_tile(t + STAGES - 1, (t + STAGES - 1) % STAGES);
        asm volatile("cp.async.wait_group %0;" :: "n"(STAGES-1));
        __syncthreads();
        uint32_t base = sb + buf*TILEB;

        unsigned bh[NFR][4], bl[NFR][4];   // [s*2],[s*2+1] = k16 sub-step regs
#pragma unroll
        for (int nf = 0; nf < NFR; nf++) {
            ldsm4(bh[nf], base + boff[nf]);
            ldsm4(bl[nf], base + boff[nf] + BN*80);
        }
#pragma unroll
        for (int s = 0; s < 2; s++) {
            unsigned rah[MFR][4], ral[MFR][4];
#pragma unroll
            for (int mf = 0; mf < MFR; mf++) {
                ldsm4(rah[mf], base + aoff[mf] + s*32);
                ldsm4(ral[mf], base + aoff[mf] + BM*80 + s*32);
            }
#pragma unroll
            for (int nf = 0; nf < NFR; nf++) {
                unsigned b0 = bh[nf][s*2], b1 = bh[nf][s*2+1];
                unsigned c0 = bl[nf][s*2], c1 = bl[nf][s*2+1];
#pragma unroll
                for (int mf = 0; mf < MFR; mf++) {
                    MMA16816(acc[mf][nf], rah[mf], b0, b1);
                    MMA16816(acc[mf][nf], rah[mf], c0, c1);
                    MMA16816(acc[mf][nf], ral[mf], b0, b1);
                }
            }
        }
        __syncthreads();
    }

#pragma unroll
    for (int mf = 0; mf < MFR; mf++) {
        int lrow = wm*(MFR*16) + mf*16 + g;
        unsigned long long rb0 = 0ULL, rb1 = 0ULL;
#pragma unroll
        for (int nf = 0; nf < NFR; nf++) {
            int row = row0 + lrow;
            int col = col0 + wn*(NFR*8) + nf*8 + tg*2;
            float2 bb = *(const float2*)(bias + col);
            float o0 = acc[mf][nf][0] + bb.x;
            float o1 = acc[mf][nf][1] + bb.y;
            float o2 = acc[mf][nf][2] + bb.x;
            float o3 = acc[mf][nf][3] + bb.y;
            if (MODE == 0) {
                if (res) {
                    float2 r0 = *(const float2*)(res + (size_t)row*Nd + col);
                    float2 r1 = *(const float2*)(res + (size_t)(row+8)*Nd + col);
                    o0 += r0.x; o1 += r0.y; o2 += r1.x; o3 += r1.y;
                }
                *(float2*)(Cm + (size_t)row*Nd + col)     = make_float2(o0, o1);
                *(float2*)(Cm + (size_t)(row+8)*Nd + col) = make_float2(o2, o3);
            } else if (MODE == 1) {
                float tv, u;
                tv = o0; u = 0.7978845608028654f*(tv + 0.044715f*tv*tv*tv);
                o0 = 0.5f*tv*(1.0f + tanhf(u));
                tv = o1; u = 0.7978845608028654f*(tv + 0.044715f*tv*tv*tv);
                o1 = 0.5f*tv*(1.0f + tanhf(u));
                tv = o2; u = 0.7978845608028654f*(tv + 0.044715f*tv*tv*tv);
                o2 = 0.5f*tv*(1.0f + tanhf(u));
                tv = o3; u = 0.7978845608028654f*(tv + 0.044715f*tv*tv*tv);
                o3 = 0.5f*tv*(1.0f + tanhf(u));
                split2(o0, o1, Chh + (size_t)row*Nd + col,     Cll + (size_t)row*Nd + col);
                split2(o2, o3, Chh + (size_t)(row+8)*Nd + col, Cll + (size_t)(row+8)*Nd + col);
            } else {  // MODE 2
                *(float2*)(Cm + (size_t)row*Nd + col)     = make_float2(o0, o1);
                *(float2*)(Cm + (size_t)(row+8)*Nd + col) = make_float2(o2, o3);
                unsigned c0 = (unsigned)row * (unsigned)V_ + (unsigned)col;
                unsigned c1 = (unsigned)(row+8) * (unsigned)V_ + (unsigned)col;
                unsigned long long p;
                p = packkey(o0 + gumbel_at(c0),    col);     if (p > rb0) rb0 = p;
                p = packkey(o1 + gumbel_at(c0+1u), col+1);   if (p > rb0) rb0 = p;
                p = packkey(o2 + gumbel_at(c1),    col);     if (p > rb1) rb1 = p;
                p = packkey(o3 + gumbel_at(c1+1u), col+1);   if (p > rb1) rb1 = p;
            }
        }
        if (MODE == 2) {
            atomicMax(&sbest[lrow], rb0);
            atomicMax(&sbest[lrow+8], rb1);
        }
    }
    if (MODE == 2) {
        __syncthreads();
        for (int i = tid; i < BM; i += THREADS)
            if (sbest[i]) atomicMax(&am[row0 + i], sbest[i]);
    }
}

#define SMEM_B128 (2 * (2*(128+128)) * 80)            // 81920 (2 stages)
#define SMEM_B128_AM (SMEM_B128 + 128*8)              // 82944
#define SMEM_B64  (4 * (2*(64+64)) * 80)              // 81920 (4 stages)

__global__ __launch_bounds__(256) void bmma128_gelu_k(
    const __nv_bfloat16* __restrict__ Ah, const __nv_bfloat16* __restrict__ Al,
    const __nv_bfloat16* __restrict__ Bh, const __nv_bfloat16* __restrict__ Bl,
    const float* __restrict__ bias,
    __nv_bfloat16* __restrict__ Chh, __nv_bfloat16* __restrict__ Cll,
    int Nd, int Kd)
{
    bmma_body<128,128,256,2,4,1,2>(Ah, Al, Bh, Bl, bias, nullptr, nullptr,
                                   Chh, Cll, nullptr, Nd, Kd);
}

__global__ __launch_bounds__(256) void bmma128_logits_k(
    const __nv_bfloat16* __restrict__ Ah, const __nv_bfloat16* __restrict__ Al,
    const __nv_bfloat16* __restrict__ Bh, const __nv_bfloat16* __restrict__ Bl,
    const float* __restrict__ bias, float* __restrict__ Cm,
    unsigned long long* __restrict__ am, int Nd, int Kd)
{
    bmma_body<128,128,256,2,4,2,2>(Ah, Al, Bh, Bl, bias, nullptr, Cm,
                                   nullptr, nullptr, am, Nd, Kd);
}

__global__ __launch_bounds__(256) void bmma64_k(
    const __nv_bfloat16* __restrict__ Ah, const __nv_bfloat16* __restrict__ Al,
    const __nv_bfloat16* __restrict__ Bh, const __nv_bfloat16* __restrict__ Bl,
    const float* __restrict__ bias, const float* __restrict__ res,
    float* __restrict__ Cm, int Nd, int Kd)
{
    bmma_body<64,64,256,2,4,0,4>(Ah, Al, Bh, Bl, bias, res, Cm,
                                 nullptr, nullptr, nullptr, Nd, Kd);
}

__global__ __launch_bounds__(256) void bmma64_qkv_k(
    const __nv_bfloat16* __restrict__ Ah, const __nv_bfloat16* __restrict__ Al,
    const __nv_bfloat16* __restrict__ Whi, const __nv_bfloat16* __restrict__ Wlo,
    const float* __restrict__ bq, const float* __restrict__ bk, const float* __restrict__ bv,
    float* __restrict__ q, float* __restrict__ k, float* __restrict__ v)
{
    int z = blockIdx.z;
    const __nv_bfloat16* Bh = Whi + (size_t)z * WQKVO_SZ;
    const __nv_bfloat16* Bl = Wlo + (size_t)z * WQKVO_SZ;
    const float* b = (z == 0) ? bq : (z == 1) ? bk : bv;
    float*       o = (z == 0) ? q  : (z == 1) ? k  : v;
    bmma_body<64,64,256,2,4,0,4>(Ah, Al, Bh, Bl, b, nullptr, o,
                                 nullptr, nullptr, nullptr, D_, D_);
}

// ---------------- RoPE + elu+1 feature map, in place ----------------------
__global__ __launch_bounds__(256) void rope_elu_k(float* __restrict__ q,
                                                  float* __restrict__ k,
                                                  const float* __restrict__ mask)
{
    int row = blockIdx.x;
    int s = row % S_;
    int tid = threadIdx.x;
    int h = tid >> 5;
    int j = tid & 31;
    float inv = expf(-(float)j * (9.210340371976184f / 32.0f));
    float ang = (float)s * inv;
    float sn, cs;
    sincosf(ang, &sn, &cs);
    size_t o1 = (size_t)row*D_ + h*DH_ + j;
    size_t o2 = o1 + 32;

    float q1 = q[o1], q2 = q[o2];
    float rq1 = q1*cs - q2*sn;
    float rq2 = q2*cs + q1*sn;
    q[o1] = rq1 > 0.f ? rq1 + 1.f : expf(rq1);
    q[o2] = rq2 > 0.f ? rq2 + 1.f : expf(rq2);

    float m = mask[row];
    float k1 = k[o1], k2 = k[o2];
    float rk1 = k1*cs - k2*sn;
    float rk2 = k2*cs + k1*sn;
    k[o1] = (rk1 > 0.f ? rk1 + 1.f : expf(rk1)) * m;
    k[o2] = (rk2 > 0.f ? rk2 + 1.f : expf(rk2)) * m;
}

// ---------------- attention pass A: per-chunk K^T V and sum(k) ------------
__global__ __launch_bounds__(256) void attn_local_k(const float* __restrict__ k,
                                                    const float* __restrict__ v,
                                                    float* __restrict__ kvst,
                                                    float* __restrict__ zst)
{
    int blk = blockIdx.x;
    int c = blk % NCH;
    int h = (blk / NCH) % H_;
    int b = blk / (NCH * H_);
    __shared__ float Ks[64][64];
    __shared__ float Vs[64][64];
    int tid = threadIdx.x;
    size_t rowbase = (size_t)(b*S_ + c*TCH);
    for (int it = tid; it < 64*16; it += 256) {
        int t = it >> 4;
        int d4 = (it & 15) << 2;
        size_t goff = (rowbase + t)*D_ + h*DH_ + d4;
        *(float4*)&Ks[t][d4] = *(const float4*)(k + goff);
        *(float4*)&Vs[t][d4] = *(const float4*)(v + goff);
    }
    __syncthreads();
    int d  = tid & 63;
    int eg = tid >> 6;
    int e0 = eg << 4;
    float acc[16];
#pragma unroll
    for (int ii = 0; ii < 16; ii++) acc[ii] = 0.f;
    float z = 0.f;
    for (int t = 0; t < 64; t++) {
        float kv = Ks[t][d];
        z += kv;
#pragma unroll
        for (int e = 0; e < 16; e += 4) {
            float4 vv = *(float4*)&Vs[t][e0 + e];
            acc[e]   = fmaf(kv, vv.x, acc[e]);
            acc[e+1] = fmaf(kv, vv.y, acc[e+1]);
            acc[e+2] = fmaf(kv, vv.z, acc[e+2]);
            acc[e+3] = fmaf(kv, vv.w, acc[e+3]);
        }
    }
    float* kvout = kvst + ((size_t)blk << 12) + (d << 6) + e0;
#pragma unroll
    for (int ii = 0; ii < 16; ii++) kvout[ii] = acc[ii];
    if (eg == 0) zst[blk*64 + d] = z;
}

// ---------------- attention pass: exclusive prefix over chunks ------------
// grid (B_*H_, 4): each y-part scans 1024 of the 4096 kv elements
__global__ __launch_bounds__(256) void attn_prefix_k(float* __restrict__ kvst,
                                                     float* __restrict__ zst)
{
    int bh = blockIdx.x;
    int part = blockIdx.y;
    int tid = threadIdx.x;
    float* base = kvst + (size_t)bh * NCH * 4096;
    for (int idx = part*1024 + tid; idx < (part+1)*1024; idx += 256) {
        float acc = 0.f;
        for (int c2 = 0; c2 < NCH; c2++) {
            float* pp = base + (size_t)c2*4096 + idx;
            float t = *pp;
            *pp = acc;
            acc += t;
        }
    }
    if (part == 0) {
        float* zb = zst + bh * NCH * 64;
        for (int idx = tid; idx < 64; idx += 256) {
            float acc = 0.f;
            for (int c2 = 0; c2 < NCH; c2++) {
                float* pp = zb + c2*64 + idx;
                float t = *pp;
                *pp = acc;
                acc += t;
            }
        }
    }
}

// ---------------- attention pass B: intra + inter, write split a ----------
#define ATTN_SMEM ((4*64*68 + 64)*4)
__global__ __launch_bounds__(256) void attn_out_k(const float* __restrict__ q,
                                                  const float* __restrict__ k,
                                                  const float* __restrict__ v,
                                                  const float* __restrict__ kvst,
                                                  const float* __restrict__ zst,
                                                  __nv_bfloat16* __restrict__ ah,
                                                  __nv_bfloat16* __restrict__ al)
{
    extern __shared__ float sm[];
    float* Qs = sm;
    float* Ks = sm + 64*68;
    float* Vs = sm + 2*64*68;
    float* Ss = sm + 3*64*68;
    float* zp = sm + 4*64*68;
    int blk = blockIdx.x;
    int c = blk % NCH;
    int h = (blk / NCH) % H_;
    int b = blk / (NCH * H_);
    int tid = threadIdx.x;
    size_t rowbase = (size_t)(b*S_ + c*TCH);
    for (int it = tid; it < 64*16; it += 256) {
        int t = it >> 4;
        int d4 = (it & 15) << 2;
        size_t goff = (rowbase + t)*D_ + h*DH_ + d4;
        *(float4*)&Qs[t*68 + d4] = *(const float4*)(q + goff);
        *(float4*)&Ks[t*68 + d4] = *(const float4*)(k + goff);
        *(float4*)&Vs[t*68 + d4] = *(const float4*)(v + goff);
        *(float4*)&Ss[t*68 + d4] = *(const float4*)(kvst + ((size_t)blk << 12) + (t << 6) + d4);
    }
    if (tid < 64) zp[tid] = zst[blk*64 + tid];
    __syncthreads();

    int i  = tid >> 2;
    int p  = tid & 3;
    int e0 = p << 4;
    float acc[16];
#pragma unroll
    for (int ii = 0; ii < 16; ii++) acc[ii] = 0.f;
    float den = 0.f;

    for (int j = 0; j <= i; j++) {
        float a = 0.f;
#pragma unroll
        for (int d = 0; d < 64; d += 4) {
            float4 qq = *(float4*)&Qs[i*68 + d];
            float4 kk = *(float4*)&Ks[j*68 + d];
            a = fmaf(qq.x, kk.x, a); a = fmaf(qq.y, kk.y, a);
            a = fmaf(qq.z, kk.z, a); a = fmaf(qq.w, kk.w, a);
        }
        den += a;
#pragma unroll
        for (int e = 0; e < 16; e += 4) {
            float4 vv = *(float4*)&Vs[j*68 + e0 + e];
            acc[e]   = fmaf(a, vv.x, acc[e]);
            acc[e+1] = fmaf(a, vv.y, acc[e+1]);
            acc[e+2] = fmaf(a, vv.z, acc[e+2]);
            acc[e+3] = fmaf(a, vv.w, acc[e+3]);
        }
    }
#pragma unroll 4
    for (int d = 0; d < 64; d++) {
        float qd = Qs[i*68 + d];
        den = fmaf(qd, zp[d], den);
#pragma unroll
        for (int e = 0; e < 16; e += 4) {
            float4 ss = *(float4*)&Ss[d*68 + e0 + e];
            acc[e]   = fmaf(qd, ss.x, acc[e]);
            acc[e+1] = fmaf(qd, ss.y, acc[e+1]);
            acc[e+2] = fmaf(qd, ss.z, acc[e+2]);
            acc[e+3] = fmaf(qd, ss.w, acc[e+3]);
        }
    }
    float invd = 1.0f / (den + 1e-6f);
    size_t obase = (rowbase + i)*D_ + h*DH_ + e0;
#pragma unroll
    for (int e = 0; e < 16; e += 2)
        split2(acc[e]*invd, acc[e+1]*invd, ah + obase + e, al + obase + e);
}

// ---------------- conditional LayerNorm (+ split) --------------------------
__global__ __launch_bounds__(128) void cond_ln_k(const float* __restrict__ in,
                                                 float* __restrict__ outp,
                                                 __nv_bfloat16* __restrict__ hi,
                                                 __nv_bfloat16* __restrict__ lo,
                                                 const float* __restrict__ gt,
                                                 const float* __restrict__ bt,
                                                 const int* __restrict__ cond)
{
    int row = blockIdx.x;
    int tid = threadIdx.x;
    float4 xv = *(const float4*)(in + (size_t)row*D_ + tid*4);
    float s  = xv.x + xv.y + xv.z + xv.w;
    float ss = xv.x*xv.x + xv.y*xv.y + xv.z*xv.z + xv.w*xv.w;
    __shared__ float r1[4], r2[4];
    for (int o = 16; o; o >>= 1) {
        s  += __shfl_down_sync(0xFFFFFFFFu, s,  o);
        ss += __shfl_down_sync(0xFFFFFFFFu, ss, o);
    }
    int w = tid >> 5;
    if ((tid & 31) == 0) { r1[w] = s; r2[w] = ss; }
    __syncthreads();
    float st  = r1[0] + r1[1] + r1[2] + r1[3];
    float sst = r2[0] + r2[1] + r2[2] + r2[3];
    float mu  = st * (1.0f / D_);
    float var = sst * (1.0f / D_) - mu*mu;
    float rs  = rsqrtf(var + 1e-5f);
    int cc = cond[row / S_];
    float4 g4 = *(const float4*)(gt + (size_t)cc*D_ + tid*4);
    float4 b4 = *(const float4*)(bt + (size_t)cc*D_ + tid*4);
    float4 o4;
    o4.x = (xv.x - mu)*rs*g4.x + b4.x;
    o4.y = (xv.y - mu)*rs*g4.y + b4.y;
    o4.z = (xv.z - mu)*rs*g4.z + b4.z;
    o4.w = (xv.w - mu)*rs*g4.w + b4.w;
    size_t off = (size_t)row*D_ + tid*4;
    *(float4*)(outp + off) = o4;
    split2(o4.x, o4.y, hi + off,     lo + off);
    split2(o4.z, o4.w, hi + off + 2, lo + off + 2);
}

__global__ __launch_bounds__(256) void am_init_k(unsigned long long* __restrict__ am)
{
    int i = blockIdx.x * 256 + threadIdx.x;
    if (i < M_) am[i] = 0ULL;
}

__global__ __launch_bounds__(256) void onehot_k(const unsigned long long* __restrict__ am,
                                                float* __restrict__ oh)
{
    int r = blockIdx.x * 256 + threadIdx.x;
    if (r >= M_) return;
    unsigned low = (unsigned)(am[r] & 0xFFFFFFFFull);
    unsigned v = 0xFFFFFFFFu - low;
    oh[(size_t)r * V_ + v] = 1.0f;
}

// ---------------- launch ---------------------------------------------------
extern "C" void kernel_launch(void* const* d_in, const int* in_sizes, int n_in,
                              void* d_out, int out_size)
{
    const int*   inputs = (const int*)  d_in[0];
    const int*   cond   = (const int*)  d_in[1];
    const float* mask   = (const float*)d_in[2];
    const float* emb    = (const float*)d_in[4];
    const float* pos    = (const float*)d_in[5];
    const float* Wq     = (const float*)d_in[6];
    const float* bq     = (const float*)d_in[7];
    const float* Wk     = (const float*)d_in[8];
    const float* bk     = (const float*)d_in[9];
    const float* Wv     = (const float*)d_in[10];
    const float* bv     = (const float*)d_in[11];
    const float* Wo     = (const float*)d_in[12];
    const float* bo     = (const float*)d_in[13];
    const float* W1     = (const float*)d_in[14];
    const float* b1     = (const float*)d_in[15];
    const float* W2     = (const float*)d_in[16];
    const float* b2     = (const float*)d_in[17];
    const float* cn1g   = (const float*)d_in[18];
    const float* cn1b   = (const float*)d_in[19];
    const float* cn2g   = (const float*)d_in[20];
    const float* cn2b   = (const float*)d_in[21];
    const float* ng     = (const float*)d_in[22];
    const float* nb     = (const float*)d_in[23];
    const float* Wout   = (const float*)d_in[24];
    const float* bout   = (const float*)d_in[25];
    float* out = (float*)d_out;

    float *xp, *x1p, *qp, *kp, *vp, *kvp, *zp;
    unsigned long long* amp;
    __nv_bfloat16 *wb, *ah, *al, *gh, *gl;
    cudaGetSymbolAddress((void**)&xp,  g_x);
    cudaGetSymbolAddress((void**)&x1p, g_x1);
    cudaGetSymbolAddress((void**)&qp,  g_q);
    cudaGetSymbolAddress((void**)&kp,  g_k);
    cudaGetSymbolAddress((void**)&vp,  g_v);
    cudaGetSymbolAddress((void**)&kvp, g_kv);
    cudaGetSymbolAddress((void**)&zp,  g_z);
    cudaGetSymbolAddress((void**)&amp, g_am);
    cudaGetSymbolAddress((void**)&wb,  g_wb);
    cudaGetSymbolAddress((void**)&ah,  g_ah);
    cudaGetSymbolAddress((void**)&al,  g_al);
    cudaGetSymbolAddress((void**)&gh,  g_gh);
    cudaGetSymbolAddress((void**)&gl,  g_gl);
    __nv_bfloat16* wbl = wb + (size_t)TOTW;

    cudaFuncSetAttribute(attn_out_k, cudaFuncAttributeMaxDynamicSharedMemorySize, ATTN_SMEM);
    cudaFuncSetAttribute(bmma128_gelu_k,   cudaFuncAttributeMaxDynamicSharedMemorySize, SMEM_B128);
    cudaFuncSetAttribute(bmma128_logits_k, cudaFuncAttributeMaxDynamicSharedMemorySize, SMEM_B128_AM);
    cudaFuncSetAttribute(bmma64_k,     cudaFuncAttributeMaxDynamicSharedMemorySize, SMEM_B64);
    cudaFuncSetAttribute(bmma64_qkv_k, cudaFuncAttributeMaxDynamicSharedMemorySize, SMEM_B64);

    // ---- weight conversion: 4 chip-filling launches ----
    dim3 wt(32, 8);
    wsplit_qkvo_k<<<dim3(16,16,32), wt>>>(Wq, Wk, Wv, Wo, wb, wbl);
    wsplit_w1_k  <<<dim3(64,16, 8), wt>>>(W1, wb, wbl);
    wsplit_w2_k  <<<dim3(16,64, 8), wt>>>(W2, wb, wbl);
    wsplit_wout_k<<<dim3(1000,16), wt>>>(Wout, wb + WOUT_OFF, wbl + WOUT_OFF);

    embed_k<<<M_, 128>>>(inputs, emb, pos, xp, ah, al);

    dim3 gQKV(D_/64, M_/64, 3);   // (8,32,3)
    dim3 g64 (D_/64, M_/64);      // (8,32)
    dim3 gF  (F_/128, M_/128);    // (16,16)
    dim3 gPre(B_*H_, 4);          // (16,4)

    for (int l = 0; l < L_; l++) {
        size_t base = (size_t)l * LW;
        bmma64_qkv_k<<<gQKV, 256, SMEM_B64>>>(ah, al, wb + base, wbl + base,
                                    bq + l*D_, bk + l*D_, bv + l*D_, qp, kp, vp);
        rope_elu_k<<<M_, 256>>>(qp, kp, mask);
        attn_local_k<<<B_*H_*NCH, 256>>>(kp, vp, kvp, zp);
        attn_prefix_k<<<gPre, 256>>>(kvp, zp);
        attn_out_k<<<B_*H_*NCH, 256, ATTN_SMEM>>>(qp, kp, vp, kvp, zp, ah, al);
        bmma64_k<<<g64, 256, SMEM_B64>>>(ah, al, wb + base + 3*WQKVO_SZ, wbl + base + 3*WQKVO_SZ,
                               bo + l*D_, xp, xp, D_, D_);
        cond_ln_k<<<M_, 128>>>(xp, x1p, ah, al,
                               cn1g + (size_t)l*C_*D_, cn1b + (size_t)l*C_*D_, cond);
        bmma128_gelu_k<<<gF, 256, SMEM_B128>>>(ah, al, wb + base + 4*WQKVO_SZ, wbl + base + 4*WQKVO_SZ,
                                    b1 + l*F_, gh, gl, F_, D_);
        bmma64_k<<<g64, 256, SMEM_B64>>>(gh, gl, wb + base + 4*WQKVO_SZ + (size_t)D_*F_,
                               wbl + base + 4*WQKVO_SZ + (size_t)D_*F_,
                               b2 + l*D_, x1p, xp, D_, F_);
        cond_ln_k<<<M_, 128>>>(xp, xp, ah, al,
                               cn2g + (size_t)l*C_*D_, cn2b + (size_t)l*C_*D_, cond);
    }
    cond_ln_k<<<M_, 128>>>(xp, xp, ah, al, ng, nb, cond);

    am_init_k<<<(M_ + 255)/256, 256>>>(amp);
    dim3 gV(V_/128, M_/128);     // (250,16)
    bmma128_logits_k<<<gV, 256, SMEM_B128_AM>>>(ah, al, wb + WOUT_OFF, wbl + WOUT_OFF,
                                  bout, out, amp, V_, D_);
    cudaMemsetAsync(out + NTOT, 0, (size_t)NTOT * sizeof(float), 0);
    onehot_k<<<(M_ + 255)/256, 256>>>(amp, out + NTOT);
}

// round 16
// speedup vs baseline: 1.0620x; 1.0620x over previous
#include <cuda_runtime.h>
#include <cuda_bf16.h>
#include <cstdint>
#include <math.h>

#define B_ 2
#define S_ 1024
#define D_ 512
#define H_ 8
#define DH_ 64
#define L_ 8
#define F_ 2048
#define V_ 32000
#define C_ 4
#define M_ (B_*S_)          // 2048 rows
#define TCH 64
#define NCH (S_/TCH)
#define NTOT 65536000       // M_*V_

#define WQKVO_SZ (D_*D_)
#define LW  (4*WQKVO_SZ + D_*F_ + F_*D_)
#define WOUT_OFF (L_*LW)
#define TOTW (WOUT_OFF + V_*D_)

// ---------------- scratch (device globals; no allocation allowed) ----------
__device__ float g_x [M_*D_];
__device__ float g_x1[M_*D_];
__device__ float g_q [M_*D_];
__device__ float g_k [M_*D_];
__device__ float g_v [M_*D_];
__device__ float g_kv[B_*H_*NCH*DH_*DH_];
__device__ float g_z [B_*H_*NCH*DH_];
__device__ unsigned long long g_am[M_];
__device__ __nv_bfloat16 g_wb[2ull*TOTW];   // weight hi plane, then lo plane
__device__ __nv_bfloat16 g_ah[M_*F_];       // activation hi
__device__ __nv_bfloat16 g_al[M_*F_];       // activation lo
__device__ __nv_bfloat16 g_gh[M_*F_];       // gelu(W1) hi
__device__ __nv_bfloat16 g_gl[M_*F_];       // gelu(W1) lo

// ---------------- helpers --------------------------------------------------
__device__ __forceinline__ void split2(float a, float b,
                                       __nv_bfloat16* hi, __nv_bfloat16* lo)
{
    __nv_bfloat16 h0 = __float2bfloat16(a);
    __nv_bfloat16 h1 = __float2bfloat16(b);
    *(__nv_bfloat162*)hi = __nv_bfloat162(h0, h1);
    *(__nv_bfloat162*)lo = __nv_bfloat162(__float2bfloat16(a - __bfloat162float(h0)),
                                          __float2bfloat16(b - __bfloat162float(h1)));
}

// ---------------- embedding + positional (+ split, + am init) --------------
__global__ __launch_bounds__(128) void embed_k(const int* __restrict__ inputs,
                                               const float* __restrict__ emb,
                                               const float* __restrict__ pos,
                                               float* __restrict__ x,
                                               __nv_bfloat16* __restrict__ ah,
                                               __nv_bfloat16* __restrict__ al,
                                               unsigned long long* __restrict__ am)
{
    int row = blockIdx.x;
    int s = row % S_;
    int tok = inputs[row];
    int tid = threadIdx.x;
    if (tid == 0) am[row] = 0ULL;
    float4 e = *(const float4*)(emb + (size_t)tok*D_ + tid*4);
    float4 p = *(const float4*)(pos + (size_t)s*D_ + tid*4);
    float4 o;
    o.x = e.x + p.x; o.y = e.y + p.y; o.z = e.z + p.z; o.w = e.w + p.w;
    size_t off = (size_t)row*D_ + tid*4;
    *(float4*)(x + off) = o;
    split2(o.x, o.y, ah + off,     al + off);
    split2(o.z, o.w, ah + off + 2, al + off + 2);
}

// -------- weight transpose + split core: W[K][N] fp32 -> hi/lo [N][K] -----
__device__ __forceinline__ void wsplit_tile(const float* __restrict__ W,
                                            __nv_bfloat16* __restrict__ hi,
                                            __nv_bfloat16* __restrict__ lo,
                                            int K, int N, int n0, int k0)
{
    __shared__ float t[32][33];
    int tx = threadIdx.x, ty = threadIdx.y;     // (32,8)
#pragma unroll
    for (int i = 0; i < 32; i += 8)
        t[ty+i][tx] = W[(size_t)(k0+ty+i)*N + n0+tx];
    __syncthreads();
#pragma unroll
    for (int i = 0; i < 32; i += 8) {
        float v = t[tx][ty+i];
        __nv_bfloat16 h = __float2bfloat16(v);
        __nv_bfloat16 l = __float2bfloat16(v - __bfloat162float(h));
        size_t o = (size_t)(n0+ty+i)*K + k0+tx;
        hi[o] = h; lo[o] = l;
    }
}

__global__ __launch_bounds__(256) void wsplit_qkvo_k(
    const float* __restrict__ Wq, const float* __restrict__ Wk,
    const float* __restrict__ Wv, const float* __restrict__ Wo,
    __nv_bfloat16* __restrict__ hi, __nv_bfloat16* __restrict__ lo)
{
    int z = blockIdx.z;
    int l = z >> 2, which = z & 3;
    const float* src = (which == 0) ? Wq : (which == 1) ? Wk : (which == 2) ? Wv : Wo;
    src += (size_t)l * D_ * D_;
    size_t dsto = (size_t)l * LW + (size_t)which * WQKVO_SZ;
    wsplit_tile(src, hi + dsto, lo + dsto, D_, D_, blockIdx.x*32, blockIdx.y*32);
}

__global__ __launch_bounds__(256) void wsplit_w1_k(
    const float* __restrict__ W1,
    __nv_bfloat16* __restrict__ hi, __nv_bfloat16* __restrict__ lo)
{
    int l = blockIdx.z;
    const float* src = W1 + (size_t)l * D_ * F_;
    size_t dsto = (size_t)l * LW + 4*WQKVO_SZ;
    wsplit_tile(src, hi + dsto, lo + dsto, D_, F_, blockIdx.x*32, blockIdx.y*32);
}

__global__ __launch_bounds__(256) void wsplit_w2_k(
    const float* __restrict__ W2,
    __nv_bfloat16* __restrict__ hi, __nv_bfloat16* __restrict__ lo)
{
    int l = blockIdx.z;
    const float* src = W2 + (size_t)l * F_ * D_;
    size_t dsto = (size_t)l * LW + 4*WQKVO_SZ + (size_t)D_*F_;
    wsplit_tile(src, hi + dsto, lo + dsto, F_, D_, blockIdx.x*32, blockIdx.y*32);
}

__global__ __launch_bounds__(256) void wsplit_wout_k(
    const float* __restrict__ W,
    __nv_bfloat16* __restrict__ hi, __nv_bfloat16* __restrict__ lo)
{
    wsplit_tile(W, hi, lo, D_, V_, blockIdx.x*32, blockIdx.y*32);
}

// ---------------- Threefry-2x32-20 (JAX PRNG, key (0,42)) -----------------
__device__ __forceinline__ unsigned rotl32(unsigned x, int d) {
    return __funnelshift_l(x, x, d);
}
__device__ __forceinline__ void threefry_0_42(unsigned x0, unsigned x1,
                                              unsigned& o0, unsigned& o1)
{
    const unsigned k0 = 0u, k1 = 42u;
    const unsigned k2 = 0x1BD11BDAu ^ k0 ^ k1;
    x0 += k0; x1 += k1;
#define TF_R4(ra,rb,rc,rd) \
    x0 += x1; x1 = rotl32(x1, ra); x1 ^= x0; \
    x0 += x1; x1 = rotl32(x1, rb); x1 ^= x0; \
    x0 += x1; x1 = rotl32(x1, rc); x1 ^= x0; \
    x0 += x1; x1 = rotl32(x1, rd); x1 ^= x0;
    TF_R4(13,15,26,6);  x0 += k1; x1 += k2 + 1u;
    TF_R4(17,29,16,24); x0 += k2; x1 += k0 + 2u;
    TF_R4(13,15,26,6);  x0 += k0; x1 += k1 + 3u;
    TF_R4(17,29,16,24); x0 += k1; x1 += k2 + 4u;
    TF_R4(13,15,26,6);  x0 += k2; x1 += k0 + 5u;
#undef TF_R4
    o0 = x0; o1 = x1;
}
__device__ __forceinline__ float gumbel_from_bits(unsigned bits)
{
    float f = __uint_as_float((bits >> 9) | 0x3f800000u) - 1.0f;
    f = fmaxf(f, 1.17549435e-38f);
    return -logf(-logf(f));
}
__device__ __forceinline__ unsigned long long packkey(float v, int idx)
{
    unsigned u = __float_as_uint(v);
    u = (u & 0x80000000u) ? ~u : (u | 0x80000000u);
    return ((unsigned long long)u << 32) | (unsigned)(0xFFFFFFFFu - (unsigned)idx);
}
__device__ __forceinline__ float gumbel_at(unsigned cnt)
{
    unsigned o0, o1;
    threefry_0_42(0u, cnt, o0, o1);
    return gumbel_from_bits(o0 ^ o1);   // partitionable 32-bit path
}

// ---------------- split-bf16 tensor-core GEMM (round-12 engine) ------------
// C = (Ah+Al)(Bh+Bl)^T ~= AhBh + AhBl + AlBh  (lo*lo dropped)
// MODE 0: fp32 out (+bias,+res) | MODE 1: gelu -> bf16 hi/lo | MODE 2: +gumbel argmax
#define MMA16816(d, a, b0, b1)                                              \
    asm volatile("mma.sync.aligned.m16n8k16.row.col.f32.bf16.bf16.f32 "     \
                 "{%0,%1,%2,%3}, {%4,%5,%6,%7}, {%8,%9}, {%0,%1,%2,%3};"    \
                 : "+f"(d[0]), "+f"(d[1]), "+f"(d[2]), "+f"(d[3])           \
                 : "r"(a[0]), "r"(a[1]), "r"(a[2]), "r"(a[3]),              \
                   "r"(b0), "r"(b1))

template<int BM, int BN, int THREADS, int WMS, int WNS, int MODE>
__device__ __forceinline__ void bmma_body(
    const __nv_bfloat16* __restrict__ Ah, const __nv_bfloat16* __restrict__ Al,
    const __nv_bfloat16* __restrict__ Bh, const __nv_bfloat16* __restrict__ Bl,
    const float* __restrict__ bias, const float* __restrict__ res,
    float* __restrict__ Cm,
    __nv_bfloat16* __restrict__ Chh, __nv_bfloat16* __restrict__ Cll,
    unsigned long long* __restrict__ am,
    int Nd, int Kd)
{
    constexpr int MFR = BM / (WMS * 16);
    constexpr int NFR = BN / (WNS * 8);
    __shared__ __nv_bfloat16 As[2][2][BM][24];
    __shared__ __nv_bfloat16 Bs[2][2][BN][24];
    __shared__ unsigned long long sbest[MODE == 2 ? BM : 1];

    int tid = threadIdx.x;
    int wid = tid >> 5, lane = tid & 31;
    int wm = wid % WMS, wn = wid / WMS;
    int g = lane >> 2, tg = lane & 3;
    int row0 = blockIdx.y * BM, col0 = blockIdx.x * BN;

    int lr = tid >> 1;
    int lc = (tid & 1) * 8;
    const __nv_bfloat16* pAh = Ah + (size_t)(row0+lr)*Kd + lc;
    const __nv_bfloat16* pAl = Al + (size_t)(row0+lr)*Kd + lc;
    const __nv_bfloat16* pBh = Bh + (size_t)(col0+lr)*Kd + lc;
    const __nv_bfloat16* pBl = Bl + (size_t)(col0+lr)*Kd + lc;

    float acc[MFR][NFR][4];
#pragma unroll
    for (int i = 0; i < MFR; i++)
#pragma unroll
        for (int j = 0; j < NFR; j++)
#pragma unroll
            for (int r = 0; r < 4; r++) acc[i][j][r] = 0.f;

    if (MODE == 2) {
        for (int i = tid; i < BM; i += THREADS) sbest[i] = 0ULL;
    }

    *(uint4*)&As[0][0][lr][lc] = *(const uint4*)pAh;
    *(uint4*)&As[0][1][lr][lc] = *(const uint4*)pAl;
    *(uint4*)&Bs[0][0][lr][lc] = *(const uint4*)pBh;
    *(uint4*)&Bs[0][1][lr][lc] = *(const uint4*)pBl;
    __syncthreads();

    int nt = Kd >> 4;
    for (int t = 0; t < nt; t++) {
        int cur = t & 1;
        uint4 sa, sb, sc, sd;
        bool pf = (t + 1 < nt);
        if (pf) {
            sa = *(const uint4*)(pAh + (t+1)*16);
            sb = *(const uint4*)(pAl + (t+1)*16);
            sc = *(const uint4*)(pBh + (t+1)*16);
            sd = *(const uint4*)(pBl + (t+1)*16);
        }
        unsigned rah[MFR][4], ral[MFR][4];
#pragma unroll
        for (int mf = 0; mf < MFR; mf++) {
            int r = wm*(MFR*16) + mf*16 + g;
            rah[mf][0] = *(const unsigned*)&As[cur][0][r  ][tg*2];
            rah[mf][1] = *(const unsigned*)&As[cur][0][r+8][tg*2];
            rah[mf][2] = *(const unsigned*)&As[cur][0][r  ][tg*2+8];
            rah[mf][3] = *(const unsigned*)&As[cur][0][r+8][tg*2+8];
            ral[mf][0] = *(const unsigned*)&As[cur][1][r  ][tg*2];
            ral[mf][1] = *(const unsigned*)&As[cur][1][r+8][tg*2];
            ral[mf][2] = *(const unsigned*)&As[cur][1][r  ][tg*2+8];
            ral[mf][3] = *(const unsigned*)&As[cur][1][r+8][tg*2+8];
        }
#pragma unroll
        for (int nf = 0; nf < NFR; nf++) {
            int c = wn*(NFR*8) + nf*8 + g;
            unsigned bh0 = *(const unsigned*)&Bs[cur][0][c][tg*2];
            unsigned bh1 = *(const unsigned*)&Bs[cur][0][c][tg*2+8];
            unsigned bl0 = *(const unsigned*)&Bs[cur][1][c][tg*2];
            unsigned bl1 = *(const unsigned*)&Bs[cur][1][c][tg*2+8];
#pragma unroll
            for (int mf = 0; mf < MFR; mf++) {
                MMA16816(acc[mf][nf], rah[mf], bh0, bh1);
                MMA16816(acc[mf][nf], rah[mf], bl0, bl1);
                MMA16816(acc[mf][nf], ral[mf], bh0, bh1);
            }
        }
        if (pf) {
            int nxt = cur ^ 1;
            *(uint4*)&As[nxt][0][lr][lc] = sa;
            *(uint4*)&As[nxt][1][lr][lc] = sb;
            *(uint4*)&Bs[nxt][0][lr][lc] = sc;
            *(uint4*)&Bs[nxt][1][lr][lc] = sd;
        }
        __syncthreads();
    }

#pragma unroll
    for (int mf = 0; mf < MFR; mf++) {
        int lrow = wm*(MFR*16) + mf*16 + g;
        unsigned long long rb0 = 0ULL, rb1 = 0ULL;
#pragma unroll
        for (int nf = 0; nf < NFR; nf++) {
            int row = row0 + lrow;
            int col = col0 + wn*(NFR*8) + nf*8 + tg*2;
            float2 bb = *(const float2*)(bias + col);
            float o0 = acc[mf][nf][0] + bb.x;
            float o1 = acc[mf][nf][1] + bb.y;
            float o2 = acc[mf][nf][2] + bb.x;
            float o3 = acc[mf][nf][3] + bb.y;
            if (MODE == 0) {
                if (res) {
                    float2 r0 = *(const float2*)(res + (size_t)row*Nd + col);
                    float2 r1 = *(const float2*)(res + (size_t)(row+8)*Nd + col);
                    o0 += r0.x; o1 += r0.y; o2 += r1.x; o3 += r1.y;
                }
                *(float2*)(Cm + (size_t)row*Nd + col)     = make_float2(o0, o1);
                *(float2*)(Cm + (size_t)(row+8)*Nd + col) = make_float2(o2, o3);
            } else if (MODE == 1) {
                float tv, u;
                tv = o0; u = 0.7978845608028654f*(tv + 0.044715f*tv*tv*tv);
                o0 = 0.5f*tv*(1.0f + tanhf(u));
                tv = o1; u = 0.7978845608028654f*(tv + 0.044715f*tv*tv*tv);
                o1 = 0.5f*tv*(1.0f + tanhf(u));
                tv = o2; u = 0.7978845608028654f*(tv + 0.044715f*tv*tv*tv);
                o2 = 0.5f*tv*(1.0f + tanhf(u));
                tv = o3; u = 0.7978845608028654f*(tv + 0.044715f*tv*tv*tv);
                o3 = 0.5f*tv*(1.0f + tanhf(u));
                split2(o0, o1, Chh + (size_t)row*Nd + col,     Cll + (size_t)row*Nd + col);
                split2(o2, o3, Chh + (size_t)(row+8)*Nd + col, Cll + (size_t)(row+8)*Nd + col);
            } else {  // MODE 2
                *(float2*)(Cm + (size_t)row*Nd + col)     = make_float2(o0, o1);
                *(float2*)(Cm + (size_t)(row+8)*Nd + col) = make_float2(o2, o3);
                unsigned c0 = (unsigned)row * (unsigned)V_ + (unsigned)col;
                unsigned c1 = (unsigned)(row+8) * (unsigned)V_ + (unsigned)col;
                unsigned long long p;
                p = packkey(o0 + gumbel_at(c0),    col);     if (p > rb0) rb0 = p;
                p = packkey(o1 + gumbel_at(c0+1u), col+1);   if (p > rb0) rb0 = p;
                p = packkey(o2 + gumbel_at(c1),    col);     if (p > rb1) rb1 = p;
                p = packkey(o3 + gumbel_at(c1+1u), col+1);   if (p > rb1) rb1 = p;
            }
        }
        if (MODE == 2) {
            atomicMax(&sbest[lrow], rb0);
            atomicMax(&sbest[lrow+8], rb1);
        }
    }
    if (MODE == 2) {
        __syncthreads();
        for (int i = tid; i < BM; i += THREADS)
            if (sbest[i]) atomicMax(&am[row0 + i], sbest[i]);
    }
}

__global__ __launch_bounds__(256) void bmma128_gelu_k(
    const __nv_bfloat16* __restrict__ Ah, const __nv_bfloat16* __restrict__ Al,
    const __nv_bfloat16* __restrict__ Bh, const __nv_bfloat16* __restrict__ Bl,
    const float* __restrict__ bias,
    __nv_bfloat16* __restrict__ Chh, __nv_bfloat16* __restrict__ Cll,
    int Nd, int Kd)
{
    bmma_body<128,128,256,2,4,1>(Ah, Al, Bh, Bl, bias, nullptr, nullptr,
                                 Chh, Cll, nullptr, Nd, Kd);
}

__global__ __launch_bounds__(256) void bmma128_logits_k(
    const __nv_bfloat16* __restrict__ Ah, const __nv_bfloat16* __restrict__ Al,
    const __nv_bfloat16* __restrict__ Bh, const __nv_bfloat16* __restrict__ Bl,
    const float* __restrict__ bias, float* __restrict__ Cm,
    unsigned long long* __restrict__ am, int Nd, int Kd)
{
    bmma_body<128,128,256,2,4,2>(Ah, Al, Bh, Bl, bias, nullptr, Cm,
                                 nullptr, nullptr, am, Nd, Kd);
}

__global__ __launch_bounds__(128) void bmma64_k(
    const __nv_bfloat16* __restrict__ Ah, const __nv_bfloat16* __restrict__ Al,
    const __nv_bfloat16* __restrict__ Bh, const __nv_bfloat16* __restrict__ Bl,
    const float* __restrict__ bias, const float* __restrict__ res,
    float* __restrict__ Cm, int Nd, int Kd)
{
    bmma_body<64,64,128,2,2,0>(Ah, Al, Bh, Bl, bias, res, Cm,
                               nullptr, nullptr, nullptr, Nd, Kd);
}

__global__ __launch_bounds__(128) void bmma64_qkv_k(
    const __nv_bfloat16* __restrict__ Ah, const __nv_bfloat16* __restrict__ Al,
    const __nv_bfloat16* __restrict__ Whi, const __nv_bfloat16* __restrict__ Wlo,
    const float* __restrict__ bq, const float* __restrict__ bk, const float* __restrict__ bv,
    float* __restrict__ q, float* __restrict__ k, float* __restrict__ v)
{
    int z = blockIdx.z;
    const __nv_bfloat16* Bh = Whi + (size_t)z * WQKVO_SZ;
    const __nv_bfloat16* Bl = Wlo + (size_t)z * WQKVO_SZ;
    const float* b = (z == 0) ? bq : (z == 1) ? bk : bv;
    float*       o = (z == 0) ? q  : (z == 1) ? k  : v;
    bmma_body<64,64,128,2,2,0>(Ah, Al, Bh, Bl, b, nullptr, o,
                               nullptr, nullptr, nullptr, D_, D_);
}

// ---------------- fused RoPE helpers ---------------------------------------
// rotated pair at head-dim j / j+32 (j in 0..31), position s
__device__ __forceinline__ void rope_pair(float a, float b, int j, int s,
                                          float& r1, float& r2)
{
    float inv = expf(-(float)j * (9.210340371976184f / 32.0f));
    float ang = (float)s * inv;
    float sn, cs;
    sincosf(ang, &sn, &cs);
    r1 = a*cs - b*sn;
    r2 = b*cs + a*sn;
}
__device__ __forceinline__ float elu1(float x) {
    return x > 0.f ? x + 1.f : expf(x);
}

// ---------------- attention pass A: rope(k)+mask fused, K^T V, sum(k) ------
__global__ __launch_bounds__(256) void attn_local_k(const float* __restrict__ k,
                                                    const float* __restrict__ v,
                                                    const float* __restrict__ mask,
                                                    float* __restrict__ kvst,
                                                    float* __restrict__ zst)
{
    int blk = blockIdx.x;
    int c = blk % NCH;
    int h = (blk / NCH) % H_;
    int b = blk / (NCH * H_);
    __shared__ float Ks[64][64];
    __shared__ float Vs[64][64];
    int tid = threadIdx.x;
    size_t rowbase = (size_t)(b*S_ + c*TCH);
    // V: plain load (64 x 16 float4 chunks)
    for (int it = tid; it < 64*16; it += 256) {
        int t = it >> 4;
        int d4 = (it & 15) << 2;
        *(float4*)&Vs[t][d4] = *(const float4*)(v + (rowbase + t)*D_ + h*DH_ + d4);
    }
    // K: rope + elu+1 + mask on the fly (64 x 8 float4 chunks, each does a pair)
    for (int it = tid; it < 64*8; it += 256) {
        int t = it >> 3;
        int d4 = (it & 7) << 2;
        int row = (int)rowbase + t;
        int s = c*TCH + t;
        size_t o1 = (size_t)row*D_ + h*DH_ + d4;
        float4 ka = *(const float4*)(k + o1);
        float4 kb = *(const float4*)(k + o1 + 32);
        float m = mask[row];
        float* kaa = (float*)&ka;
        float* kbb = (float*)&kb;
#pragma unroll
        for (int e = 0; e < 4; e++) {
            float r1, r2;
            rope_pair(kaa[e], kbb[e], d4 + e, s, r1, r2);
            Ks[t][d4 + e]      = elu1(r1) * m;
            Ks[t][d4 + e + 32] = elu1(r2) * m;
        }
    }
    __syncthreads();
    int d  = tid & 63;
    int eg = tid >> 6;
    int e0 = eg << 4;
    float acc[16];
#pragma unroll
    for (int ii = 0; ii < 16; ii++) acc[ii] = 0.f;
    float z = 0.f;
    for (int t = 0; t < 64; t++) {
        float kv = Ks[t][d];
        z += kv;
#pragma unroll
        for (int e = 0; e < 16; e += 4) {
            float4 vv = *(float4*)&Vs[t][e0 + e];
            acc[e]   = fmaf(kv, vv.x, acc[e]);
            acc[e+1] = fmaf(kv, vv.y, acc[e+1]);
            acc[e+2] = fmaf(kv, vv.z, acc[e+2]);
            acc[e+3] = fmaf(kv, vv.w, acc[e+3]);
        }
    }
    float* kvout = kvst + ((size_t)blk << 12) + (d << 6) + e0;
#pragma unroll
    for (int ii = 0; ii < 16; ii++) kvout[ii] = acc[ii];
    if (eg == 0) zst[blk*64 + d] = z;
}

// ---------------- attention pass: exclusive prefix over chunks -------------
// grid (B_*H_, 4): each y-part scans 1024 of the 4096 kv elements
__global__ __launch_bounds__(256) void attn_prefix_k(float* __restrict__ kvst,
                                                     float* __restrict__ zst)
{
    int bh = blockIdx.x;
    int part = blockIdx.y;
    int tid = threadIdx.x;
    float* base = kvst + (size_t)bh * NCH * 4096;
    for (int idx = part*1024 + tid; idx < (part+1)*1024; idx += 256) {
        float acc = 0.f;
        for (int c2 = 0; c2 < NCH; c2++) {
            float* pp = base + (size_t)c2*4096 + idx;
            float t = *pp;
            *pp = acc;
            acc += t;
        }
    }
    if (part == 0) {
        float* zb = zst + bh * NCH * 64;
        for (int idx = tid; idx < 64; idx += 256) {
            float acc = 0.f;
            for (int c2 = 0; c2 < NCH; c2++) {
                float* pp = zb + c2*64 + idx;
                float t = *pp;
                *pp = acc;
                acc += t;
            }
        }
    }
}

// ---------------- attention pass B: rope fused, intra+inter, split out -----
#define ATTN_SMEM ((4*64*68 + 64)*4)
__global__ __launch_bounds__(256) void attn_out_k(const float* __restrict__ q,
                                                  const float* __restrict__ k,
                                                  const float* __restrict__ v,
                                                  const float* __restrict__ mask,
                                                  const float* __restrict__ kvst,
                                                  const float* __restrict__ zst,
                                                  __nv_bfloat16* __restrict__ ah,
                                                  __nv_bfloat16* __restrict__ al)
{
    extern __shared__ float sm[];
    float* Qs = sm;
    float* Ks = sm + 64*68;
    float* Vs = sm + 2*64*68;
    float* Ss = sm + 3*64*68;
    float* zp = sm + 4*64*68;
    int blk = blockIdx.x;
    int c = blk % NCH;
    int h = (blk / NCH) % H_;
    int b = blk / (NCH * H_);
    int tid = threadIdx.x;
    size_t rowbase = (size_t)(b*S_ + c*TCH);
    // V and S: plain loads
    for (int it = tid; it < 64*16; it += 256) {
        int t = it >> 4;
        int d4 = (it & 15) << 2;
        *(float4*)&Vs[t*68 + d4] = *(const float4*)(v + (rowbase + t)*D_ + h*DH_ + d4);
        *(float4*)&Ss[t*68 + d4] = *(const float4*)(kvst + ((size_t)blk << 12) + (t << 6) + d4);
    }
    // Q and K: rope + elu+1 (+mask for K) on the fly
    for (int it = tid; it < 64*8; it += 256) {
        int t = it >> 3;
        int d4 = (it & 7) << 2;
        int row = (int)rowbase + t;
        int s = c*TCH + t;
        size_t o1 = (size_t)row*D_ + h*DH_ + d4;
        float4 qa = *(const float4*)(q + o1);
        float4 qb = *(const float4*)(q + o1 + 32);
        float4 ka = *(const float4*)(k + o1);
        float4 kb = *(const float4*)(k + o1 + 32);
        float m = mask[row];
        float* qaa = (float*)&qa; float* qbb = (float*)&qb;
        float* kaa = (float*)&ka; float* kbb = (float*)&kb;
#pragma unroll
        for (int e = 0; e < 4; e++) {
            float r1, r2;
            rope_pair(qaa[e], qbb[e], d4 + e, s, r1, r2);
            Qs[t*68 + d4 + e]      = elu1(r1);
            Qs[t*68 + d4 + e + 32] = elu1(r2);
            rope_pair(kaa[e], kbb[e], d4 + e, s, r1, r2);
            Ks[t*68 + d4 + e]      = elu1(r1) * m;
            Ks[t*68 + d4 + e + 32] = elu1(r2) * m;
        }
    }
    if (tid < 64) zp[tid] = zst[blk*64 + tid];
    __syncthreads();

    int i  = tid >> 2;
    int p  = tid & 3;
    int e0 = p << 4;
    float acc[16];
#pragma unroll
    for (int ii = 0; ii < 16; ii++) acc[ii] = 0.f;
    float den = 0.f;

    for (int j = 0; j <= i; j++) {
        float a = 0.f;
#pragma unroll
        for (int d = 0; d < 64; d += 4) {
            float4 qq = *(float4*)&Qs[i*68 + d];
            float4 kk = *(float4*)&Ks[j*68 + d];
            a = fmaf(qq.x, kk.x, a); a = fmaf(qq.y, kk.y, a);
            a = fmaf(qq.z, kk.z, a); a = fmaf(qq.w, kk.w, a);
        }
        den += a;
#pragma unroll
        for (int e = 0; e < 16; e += 4) {
            float4 vv = *(float4*)&Vs[j*68 + e0 + e];
            acc[e]   = fmaf(a, vv.x, acc[e]);
            acc[e+1] = fmaf(a, vv.y, acc[e+1]);
            acc[e+2] = fmaf(a, vv.z, acc[e+2]);
            acc[e+3] = fmaf(a, vv.w, acc[e+3]);
        }
    }
#pragma unroll 4
    for (int d = 0; d < 64; d++) {
        float qd = Qs[i*68 + d];
        den = fmaf(qd, zp[d], den);
#pragma unroll
        for (int e = 0; e < 16; e += 4) {
            float4 ss = *(float4*)&Ss[d*68 + e0 + e];
            acc[e]   = fmaf(qd, ss.x, acc[e]);
            acc[e+1] = fmaf(qd, ss.y, acc[e+1]);
            acc[e+2] = fmaf(qd, ss.z, acc[e+2]);
            acc[e+3] = fmaf(qd, ss.w, acc[e+3]);
        }
    }
    float invd = 1.0f / (den + 1e-6f);
    size_t obase = (rowbase + i)*D_ + h*DH_ + e0;
#pragma unroll
    for (int e = 0; e < 16; e += 2)
        split2(acc[e]*invd, acc[e+1]*invd, ah + obase + e, al + obase + e);
}

// ---------------- conditional LayerNorm (+ split) --------------------------
__global__ __launch_bounds__(128) void cond_ln_k(const float* __restrict__ in,
                                                 float* __restrict__ outp,
                                                 __nv_bfloat16* __restrict__ hi,
                                                 __nv_bfloat16* __restrict__ lo,
                                                 const float* __restrict__ gt,
                                                 const float* __restrict__ bt,
                                                 const int* __restrict__ cond)
{
    int row = blockIdx.x;
    int tid = threadIdx.x;
    float4 xv = *(const float4*)(in + (size_t)row*D_ + tid*4);
    float s  = xv.x + xv.y + xv.z + xv.w;
    float ss = xv.x*xv.x + xv.y*xv.y + xv.z*xv.z + xv.w*xv.w;
    __shared__ float r1[4], r2[4];
    for (int o = 16; o; o >>= 1) {
        s  += __shfl_down_sync(0xFFFFFFFFu, s,  o);
        ss += __shfl_down_sync(0xFFFFFFFFu, ss, o);
    }
    int w = tid >> 5;
    if ((tid & 31) == 0) { r1[w] = s; r2[w] = ss; }
    __syncthreads();
    float st  = r1[0] + r1[1] + r1[2] + r1[3];
    float sst = r2[0] + r2[1] + r2[2] + r2[3];
    float mu  = st * (1.0f / D_);
    float var = sst * (1.0f / D_) - mu*mu;
    float rs  = rsqrtf(var + 1e-5f);
    int cc = cond[row / S_];
    float4 g4 = *(const float4*)(gt + (size_t)cc*D_ + tid*4);
    float4 b4 = *(const float4*)(bt + (size_t)cc*D_ + tid*4);
    float4 o4;
    o4.x = (xv.x - mu)*rs*g4.x + b4.x;
    o4.y = (xv.y - mu)*rs*g4.y + b4.y;
    o4.z = (xv.z - mu)*rs*g4.z + b4.z;
    o4.w = (xv.w - mu)*rs*g4.w + b4.w;
    size_t off = (size_t)row*D_ + tid*4;
    *(float4*)(outp + off) = o4;
    split2(o4.x, o4.y, hi + off,     lo + off);
    split2(o4.z, o4.w, hi + off + 2, lo + off + 2);
}

__global__ __launch_bounds__(256) void onehot_k(const unsigned long long* __restrict__ am,
                                                float* __restrict__ oh)
{
    int r = blockIdx.x * 256 + threadIdx.x;
    if (r >= M_) return;
    unsigned low = (unsigned)(am[r] & 0xFFFFFFFFull);
    unsigned v = 0xFFFFFFFFu - low;
    oh[(size_t)r * V_ + v] = 1.0f;
}

// ---------------- launch ---------------------------------------------------
extern "C" void kernel_launch(void* const* d_in, const int* in_sizes, int n_in,
                              void* d_out, int out_size)
{
    const int*   inputs = (const int*)  d_in[0];
    const int*   cond   = (const int*)  d_in[1];
    const float* mask   = (const float*)d_in[2];
    const float* emb    = (const float*)d_in[4];
    const float* pos    = (const float*)d_in[5];
    const float* Wq     = (const float*)d_in[6];
    const float* bq     = (const float*)d_in[7];
    const float* Wk     = (const float*)d_in[8];
    const float* bk     = (const float*)d_in[9];
    const float* Wv     = (const float*)d_in[10];
    const float* bv     = (const float*)d_in[11];
    const float* Wo     = (const float*)d_in[12];
    const float* bo     = (const float*)d_in[13];
    const float* W1     = (const float*)d_in[14];
    const float* b1     = (const float*)d_in[15];
    const float* W2     = (const float*)d_in[16];
    const float* b2     = (const float*)d_in[17];
    const float* cn1g   = (const float*)d_in[18];
    const float* cn1b   = (const float*)d_in[19];
    const float* cn2g   = (const float*)d_in[20];
    const float* cn2b   = (const float*)d_in[21];
    const float* ng     = (const float*)d_in[22];
    const float* nb     = (const float*)d_in[23];
    const float* Wout   = (const float*)d_in[24];
    const float* bout   = (const float*)d_in[25];
    float* out = (float*)d_out;

    float *xp, *x1p, *qp, *kp, *vp, *kvp, *zp;
    unsigned long long* amp;
    __nv_bfloat16 *wb, *ah, *al, *gh, *gl;
    cudaGetSymbolAddress((void**)&xp,  g_x);
    cudaGetSymbolAddress((void**)&x1p, g_x1);
    cudaGetSymbolAddress((void**)&qp,  g_q);
    cudaGetSymbolAddress((void**)&kp,  g_k);
    cudaGetSymbolAddress((void**)&vp,  g_v);
    cudaGetSymbolAddress((void**)&kvp, g_kv);
    cudaGetSymbolAddress((void**)&zp,  g_z);
    cudaGetSymbolAddress((void**)&amp, g_am);
    cudaGetSymbolAddress((void**)&wb,  g_wb);
    cudaGetSymbolAddress((void**)&ah,  g_ah);
    cudaGetSymbolAddress((void**)&al,  g_al);
    cudaGetSymbolAddress((void**)&gh,  g_gh);
    cudaGetSymbolAddress((void**)&gl,  g_gl);
    __nv_bfloat16* wbl = wb + (size_t)TOTW;

    cudaFuncSetAttribute(attn_out_k, cudaFuncAttributeMaxDynamicSharedMemorySize, ATTN_SMEM);

    // ---- weight conversion: 4 chip-filling launches ----
    dim3 wt(32, 8);
    wsplit_qkvo_k<<<dim3(16,16,32), wt>>>(Wq, Wk, Wv, Wo, wb, wbl);
    wsplit_w1_k  <<<dim3(64,16, 8), wt>>>(W1, wb, wbl);
    wsplit_w2_k  <<<dim3(16,64, 8), wt>>>(W2, wb, wbl);
    wsplit_wout_k<<<dim3(1000,16), wt>>>(Wout, wb + WOUT_OFF, wbl + WOUT_OFF);

    embed_k<<<M_, 128>>>(inputs, emb, pos, xp, ah, al, amp);

    dim3 gQKV(D_/64, M_/64, 3);   // (8,32,3)
    dim3 g64 (D_/64, M_/64);      // (8,32)
    dim3 gF  (F_/128, M_/128);    // (16,16)
    dim3 gPre(B_*H_, 4);          // (16,4)

    for (int l = 0; l < L_; l++) {
        size_t base = (size_t)l * LW;
        bmma64_qkv_k<<<gQKV, 128>>>(ah, al, wb + base, wbl + base,
                                    bq + l*D_, bk + l*D_, bv + l*D_, qp, kp, vp);
        attn_local_k<<<B_*H_*NCH, 256>>>(kp, vp, mask, kvp, zp);
        attn_prefix_k<<<gPre, 256>>>(kvp, zp);
        attn_out_k<<<B_*H_*NCH, 256, ATTN_SMEM>>>(qp, kp, vp, mask, kvp, zp, ah, al);
        bmma64_k<<<g64, 128>>>(ah, al, wb + base + 3*WQKVO_SZ, wbl + base + 3*WQKVO_SZ,
                               bo + l*D_, xp, xp, D_, D_);
        cond_ln_k<<<M_, 128>>>(xp, x1p, ah, al,
                               cn1g + (size_t)l*C_*D_, cn1b + (size_t)l*C_*D_, cond);
        bmma128_gelu_k<<<gF, 256>>>(ah, al, wb + base + 4*WQKVO_SZ, wbl + base + 4*WQKVO_SZ,
                                    b1 + l*F_, gh, gl, F_, D_);
        bmma64_k<<<g64, 128>>>(gh, gl, wb + base + 4*WQKVO_SZ + (size_t)D_*F_,
                               wbl + base + 4*WQKVO_SZ + (size_t)D_*F_,
                               b2 + l*D_, x1p, xp, D_, F_);
        cond_ln_k<<<M_, 128>>>(xp, xp, ah, al,
                               cn2g + (size_t)l*C_*D_, cn2b + (size_t)l*C_*D_, cond);
    }
    cond_ln_k<<<M_, 128>>>(xp, xp, ah, al, ng, nb, cond);

    dim3 gV(V_/128, M_/128);     // (250,16)
    bmma128_logits_k<<<gV, 256>>>(ah, al, wb + WOUT_OFF, wbl + WOUT_OFF,
                                  bout, out, amp, V_, D_);
    cudaMemsetAsync(out + NTOT, 0, (size_t)NTOT * sizeof(float), 0);
    onehot_k<<<(M_ + 255)/256, 256>>>(amp, out + NTOT);
}